// round 13
// baseline (speedup 1.0000x reference)
#include <cuda_runtime.h>
#include <cuda_fp16.h>
#include <stdint.h>

#define BATCH 4
#define SEQ   2048
#define DM    1024
#define NROW  (BATCH * SEQ)
typedef __half fp16;

// ---------------- scratch (__device__ globals; no allocation) ----------------
__device__ fp16 g_x16[(size_t)BATCH*SEQ*DM];      // x single fp16
__device__ fp16 g_wt[(size_t)3*DM*DM];            // W^T single fp16: [3*DM][DM]
__device__ float g_bias[3*DM];
__device__ fp16 g_qkv[(size_t)BATCH*SEQ*3*DM];    // [B*S][3DM]: q | k | v
__device__ fp16 g_vt[(size_t)BATCH*DM*SEQ];       // V^T
__device__ fp16 g_sp[(size_t)BATCH*SEQ*SEQ];      // unnormalized exp(scores), fp16
__device__ float g_rspart[(size_t)32*NROW];       // per-(bx,warp-n) row partial sums
__device__ float g_rinv[NROW];                    // 1 / rowsum

// ---------------- helpers ----------------
__device__ __forceinline__ uint32_t s2u(const void* p) {
    uint32_t a;
    asm("{ .reg .u64 t; cvta.to.shared.u64 t, %1; cvt.u32.u64 %0, t; }" : "=r"(a) : "l"(p));
    return a;
}
__device__ __forceinline__ void ldsm4(uint32_t* r, uint32_t addr) {
    asm volatile("ldmatrix.sync.aligned.m8n8.x4.shared.b16 {%0,%1,%2,%3}, [%4];"
                 : "=r"(r[0]), "=r"(r[1]), "=r"(r[2]), "=r"(r[3]) : "r"(addr));
}
__device__ __forceinline__ void mma16816(float* d, const uint32_t* a, uint32_t b0, uint32_t b1) {
    asm volatile(
        "mma.sync.aligned.m16n8k16.row.col.f32.f16.f16.f32 "
        "{%0,%1,%2,%3}, {%4,%5,%6,%7}, {%8,%9}, {%0,%1,%2,%3};"
        : "+f"(d[0]), "+f"(d[1]), "+f"(d[2]), "+f"(d[3])
        : "r"(a[0]), "r"(a[1]), "r"(a[2]), "r"(a[3]), "r"(b0), "r"(b1));
}

// ---------------- HMMA GEMM: C = scale*(A@B^T) [+bias], single fp16 product ----------------
// Modes (exactly one output path):
//   Cf   != 0 : fp32 out, optionally scaled by rinv[row] (AV normalize)
//   Chi  != 0 : fp16 out; if rspart != 0: out = exp(scale*acc), row-partials to rspart
// CTA 128x128, BK=64, 256 threads (8 warps, warp tile 32x64), 3 stages, 2 CTAs/SM.
#define BK      64
#define TILE_B  16384                    // 128 rows * 128B
#define NSTG    3
#define GSMEM   (NSTG * 2 * TILE_B)      // 96 KB

__global__ __launch_bounds__(256, 2) void gemmw(
    const fp16* __restrict__ A, const fp16* __restrict__ B,
    const float* __restrict__ bias, float scale,
    float* __restrict__ Cf, fp16* __restrict__ Chi,
    float* __restrict__ rspart, const float* __restrict__ rinv,
    int K, int lda, int ldb, int ldc,
    size_t sA, size_t sB, size_t sC)
{
    extern __shared__ char smem[];
    const uint32_t sb = s2u(smem);
    const int tid = threadIdx.x;
    const int wid = tid >> 5, lane = tid & 31;
    const int wm = wid & 3, wn = wid >> 2;           // warp grid 4 (m) x 2 (n)
    const int m0 = blockIdx.y * 128, n0 = blockIdx.x * 128;
    const int NC = K / BK;

    const fp16* bA = A + (size_t)blockIdx.z * sA + (size_t)m0 * lda;
    const fp16* bB = B + (size_t)blockIdx.z * sB + (size_t)n0 * ldb;

    auto load_chunk = [&](int c) {
        const uint32_t stg = sb + (uint32_t)(c % NSTG) * (2 * TILE_B);
        const int k0 = c * BK;
        #pragma unroll
        for (int i = 0; i < 8; i++) {
            const int t = i >> 2;                       // 0: A, 1: B
            const int sub = tid + (i & 3) * 256;        // 0..1023
            const int row = sub >> 3, col = sub & 7;    // 128 rows x 8 16B-cols
            const int ld = t ? ldb : lda;
            const fp16* src = (t ? bB : bA) + (size_t)row * ld + k0 + col * 8;
            uint32_t off = (uint32_t)(row * 128 + col * 16);
            uint32_t dst = stg + (uint32_t)t * TILE_B + (off ^ ((off >> 3) & 0x70));
            asm volatile("cp.async.cg.shared.global [%0], [%1], 16;" :: "r"(dst), "l"(src) : "memory");
        }
        asm volatile("cp.async.commit_group;" ::: "memory");
    };

    // per-lane ldmatrix addressing (SW128 rows of 128B)
    const int rlane = (lane & 7) + ((lane >> 3) & 1) * 8;
    const uint32_t xlane = (uint32_t)((rlane & 7) * 16);
    const uint32_t kbl = (uint32_t)((lane >> 4) * 16);
    uint32_t aoff[2], boff[4], kx[4];
    #pragma unroll
    for (int mf = 0; mf < 2; mf++) aoff[mf] = (uint32_t)((wm * 32 + mf * 16 + rlane) << 7);
    #pragma unroll
    for (int g = 0; g < 4; g++) boff[g] = (uint32_t)((wn * 64 + g * 16 + rlane) << 7);
    #pragma unroll
    for (int ks = 0; ks < 4; ks++) kx[ks] = ((uint32_t)(ks * 32) + kbl) ^ xlane;

    float acc[2][8][4] = {};

    load_chunk(0);
    if (NC > 1) load_chunk(1);

    for (int c = 0; c < NC; ++c) {
        if (c + 2 < NC) asm volatile("cp.async.wait_group 1;" ::: "memory");
        else            asm volatile("cp.async.wait_group 0;" ::: "memory");
        __syncthreads();                       // chunk c visible; oldest stage free
        if (c + 2 < NC) load_chunk(c + 2);

        const uint32_t stg = sb + (uint32_t)(c % NSTG) * (2 * TILE_B);
        const uint32_t sA_ = stg, sB_ = stg + TILE_B;

        #pragma unroll
        for (int ks = 0; ks < 4; ks++) {
            uint32_t ah[2][4], bf[8][2];
            ldsm4(ah[0], sA_ + aoff[0] + kx[ks]);
            ldsm4(ah[1], sA_ + aoff[1] + kx[ks]);
            #pragma unroll
            for (int g = 0; g < 4; g++) {
                uint32_t t[4];
                ldsm4(t, sB_ + boff[g] + kx[ks]);
                bf[2*g][0] = t[0]; bf[2*g+1][0] = t[1];
                bf[2*g][1] = t[2]; bf[2*g+1][1] = t[3];
            }
            #pragma unroll
            for (int mf = 0; mf < 2; mf++)
                #pragma unroll
                for (int nf = 0; nf < 8; nf++)
                    mma16816(acc[mf][nf], ah[mf], bf[nf][0], bf[nf][1]);
        }
    }

    // ---------------- epilogue ----------------
    const size_t cb = (size_t)blockIdx.z * sC;
    if (rspart) {
        // exp(scale*acc) -> fp16, deterministic row-partial sums (no atomics)
        float rs[2][2] = {};                             // [mf][row half]
        #pragma unroll
        for (int mf = 0; mf < 2; mf++) {
            const int m = m0 + wm * 32 + mf * 16 + (lane >> 2);
            #pragma unroll
            for (int nf = 0; nf < 8; nf++) {
                const int n = n0 + wn * 64 + nf * 8 + 2 * (lane & 3);
                float e00 = __expf(acc[mf][nf][0] * scale);
                float e01 = __expf(acc[mf][nf][1] * scale);
                float e10 = __expf(acc[mf][nf][2] * scale);
                float e11 = __expf(acc[mf][nf][3] * scale);
                rs[mf][0] += e00 + e01;
                rs[mf][1] += e10 + e11;
                __half2 p0 = {__float2half(e00), __float2half(e01)};
                __half2 p1 = {__float2half(e10), __float2half(e11)};
                *reinterpret_cast<__half2*>(Chi + cb + (size_t)m * ldc + n)       = p0;
                *reinterpret_cast<__half2*>(Chi + cb + (size_t)(m + 8) * ldc + n) = p1;
            }
        }
        // reduce across the 4 lanes sharing each row (fixed order -> deterministic)
        #pragma unroll
        for (int o = 1; o < 4; o <<= 1) {
            #pragma unroll
            for (int mf = 0; mf < 2; mf++) {
                rs[mf][0] += __shfl_xor_sync(0xffffffffu, rs[mf][0], o);
                rs[mf][1] += __shfl_xor_sync(0xffffffffu, rs[mf][1], o);
            }
        }
        if ((lane & 3) == 0) {
            const int part = blockIdx.x * 2 + wn;
            #pragma unroll
            for (int mf = 0; mf < 2; mf++) {
                const int grow = blockIdx.z * SEQ + m0 + wm * 32 + mf * 16 + (lane >> 2);
                rspart[(size_t)part * NROW + grow]     = rs[mf][0];
                rspart[(size_t)part * NROW + grow + 8] = rs[mf][1];
            }
        }
        return;
    }
    #pragma unroll
    for (int mf = 0; mf < 2; mf++) {
        const int m = m0 + wm * 32 + mf * 16 + (lane >> 2);
        float i0 = 1.f, i1 = 1.f;
        if (rinv) {
            i0 = rinv[blockIdx.z * SEQ + m];
            i1 = rinv[blockIdx.z * SEQ + m + 8];
        }
        #pragma unroll
        for (int nf = 0; nf < 8; nf++) {
            const int n = n0 + wn * 64 + nf * 8 + 2 * (lane & 3);
            const float b0 = bias ? bias[n] : 0.f;
            const float b1 = bias ? bias[n + 1] : 0.f;
            float v00 = acc[mf][nf][0] * scale * i0 + b0;
            float v01 = acc[mf][nf][1] * scale * i0 + b1;
            float v10 = acc[mf][nf][2] * scale * i1 + b0;
            float v11 = acc[mf][nf][3] * scale * i1 + b1;
            if (Cf) {
                float2 o0 = {v00, v01}, o1 = {v10, v11};
                *reinterpret_cast<float2*>(Cf + cb + (size_t)m * ldc + n)       = o0;
                *reinterpret_cast<float2*>(Cf + cb + (size_t)(m + 8) * ldc + n) = o1;
            } else {
                __half2 ph0 = {__float2half(v00), __float2half(v01)};
                __half2 ph1 = {__float2half(v10), __float2half(v11)};
                *reinterpret_cast<__half2*>(Chi + cb + (size_t)m * ldc + n)       = ph0;
                *reinterpret_cast<__half2*>(Chi + cb + (size_t)(m + 8) * ldc + n) = ph1;
            }
        }
    }
}

// ---------------- aux kernels ----------------
__global__ __launch_bounds__(256) void conv_f16(const float* __restrict__ in,
                                                fp16* __restrict__ o, int n4)
{
    int i = blockIdx.x * 256 + threadIdx.x;
    if (i >= n4) return;
    float4 v = reinterpret_cast<const float4*>(in)[i];
    __align__(8) fp16 h[4];
    h[0] = __float2half(v.x); h[1] = __float2half(v.y);
    h[2] = __float2half(v.z); h[3] = __float2half(v.w);
    reinterpret_cast<uint2*>(o)[i] = *reinterpret_cast<uint2*>(h);
}

__global__ void concat_bias(const float* a, const float* b, const float* c, float* o)
{
    int i = blockIdx.x * 256 + threadIdx.x;
    if (i < DM)            o[i] = a[i];
    else if (i < 2 * DM)   o[i] = b[i - DM];
    else if (i < 3 * DM)   o[i] = c[i - 2 * DM];
}

// W [K=DM, N=DM] fp32 -> wt fp16 [N, K] (transposed), z selects Wq/Wk/Wv
__global__ void transpose_w_f16(const float* __restrict__ Wq, const float* __restrict__ Wk,
                                const float* __restrict__ Wv, fp16* __restrict__ wt)
{
    __shared__ float t[32][33];
    const float* W = blockIdx.z == 0 ? Wq : blockIdx.z == 1 ? Wk : Wv;
    fp16* o = wt + (size_t)blockIdx.z * DM * DM;
    const int n0 = blockIdx.x * 32, k0 = blockIdx.y * 32;
    const int tx = threadIdx.x, ty = threadIdx.y;
    #pragma unroll
    for (int r = 0; r < 4; r++)
        t[ty + 8 * r][tx] = W[(size_t)(k0 + ty + 8 * r) * DM + n0 + tx];
    __syncthreads();
    #pragma unroll
    for (int r = 0; r < 4; r++)
        o[(size_t)(n0 + ty + 8 * r) * DM + k0 + tx] = __float2half(t[tx][ty + 8 * r]);
}

// V slice of [B][SEQ][3*DM] (fp16, stride ldin) -> [B][DM][SEQ] fp16 transpose
__global__ void transpose_f16(const fp16* __restrict__ in, fp16* __restrict__ out, int ldin)
{
    __shared__ fp16 t[32][33];
    const size_t ib = (size_t)blockIdx.z * SEQ * ldin;
    const size_t ob = (size_t)blockIdx.z * DM * SEQ;
    const int s0 = blockIdx.y * 32, d0 = blockIdx.x * 32;
    const int tx = threadIdx.x, ty = threadIdx.y;
    #pragma unroll
    for (int r = 0; r < 4; r++)
        t[ty + 8 * r][tx] = in[ib + (size_t)(s0 + ty + 8 * r) * ldin + d0 + tx];
    __syncthreads();
    #pragma unroll
    for (int r = 0; r < 4; r++)
        out[ob + (size_t)(d0 + ty + 8 * r) * SEQ + s0 + tx] = t[tx][ty + 8 * r];
}

// sum 32 row-partials per row -> 1/rowsum (fixed order -> deterministic)
__global__ __launch_bounds__(256) void finalize_rsum(const float* __restrict__ part,
                                                     float* __restrict__ inv)
{
    int r = blockIdx.x * 256 + threadIdx.x;
    if (r >= NROW) return;
    float s = 0.f;
    #pragma unroll
    for (int p = 0; p < 32; p++) s += part[(size_t)p * NROW + r];
    inv[r] = 1.f / s;
}

// ---------------- launcher ----------------
extern "C" void kernel_launch(void* const* d_in, const int* in_sizes, int n_in,
                              void* d_out, int out_size)
{
    const float* x  = (const float*)d_in[0];
    const float* Wq = (const float*)d_in[1];
    const float* bq = (const float*)d_in[2];
    const float* Wk = (const float*)d_in[3];
    const float* bk = (const float*)d_in[4];
    const float* Wv = (const float*)d_in[5];
    const float* bv = (const float*)d_in[6];
    float* out = (float*)d_out;

    fp16 *x16, *wt, *qkv, *vt, *sp;
    float *bias, *rspart, *rinv;
    cudaGetSymbolAddress((void**)&x16, g_x16);
    cudaGetSymbolAddress((void**)&wt, g_wt);
    cudaGetSymbolAddress((void**)&qkv, g_qkv);
    cudaGetSymbolAddress((void**)&vt, g_vt);
    cudaGetSymbolAddress((void**)&sp, g_sp);
    cudaGetSymbolAddress((void**)&bias, g_bias);
    cudaGetSymbolAddress((void**)&rspart, g_rspart);
    cudaGetSymbolAddress((void**)&rinv, g_rinv);

    cudaFuncSetAttribute(gemmw, cudaFuncAttributeMaxDynamicSharedMemorySize, GSMEM);

    const int M = BATCH * SEQ;

    // 1. convert x; transpose W; concat bias
    conv_f16<<<(M * DM / 4 + 255) / 256, 256>>>(x, x16, M * DM / 4);
    transpose_w_f16<<<dim3(DM / 32, DM / 32, 3), dim3(32, 8)>>>(Wq, Wk, Wv, wt);
    concat_bias<<<(3 * DM + 255) / 256, 256>>>(bq, bk, bv, bias);

    // 2. fused QKV projection: [8192, 3072] = x16 @ wt^T + bias
    gemmw<<<dim3(3 * DM / 128, M / 128, 1), 256, GSMEM>>>(
        x16, wt, bias, 1.f,
        nullptr, qkv, nullptr, nullptr,
        DM, DM, DM, 3 * DM, 0, 0, 0);

    // 3. V^T
    transpose_f16<<<dim3(DM / 32, SEQ / 32, BATCH), dim3(32, 8)>>>(qkv + 2 * DM, vt, 3 * DM);

    // 4. exp(scale * Q @ K^T) -> fp16 (unnormalized) + row-partial sums
    gemmw<<<dim3(SEQ / 128, SEQ / 128, BATCH), 256, GSMEM>>>(
        qkv, qkv + DM, nullptr, 0.03125f,
        nullptr, sp, rspart, nullptr,
        DM, 3 * DM, 3 * DM, SEQ,
        (size_t)SEQ * 3 * DM, (size_t)SEQ * 3 * DM, (size_t)SEQ * SEQ);

    // 5. 1/rowsum
    finalize_rsum<<<(NROW + 255) / 256, 256>>>(rspart, rinv);

    // 6. out = (exp @ V) * rinv[row]
    gemmw<<<dim3(DM / 128, SEQ / 128, BATCH), 256, GSMEM>>>(
        sp, vt, nullptr, 1.f,
        out, nullptr, nullptr, rinv,
        SEQ, SEQ, SEQ, DM,
        (size_t)SEQ * SEQ, (size_t)DM * SEQ, (size_t)SEQ * DM);
}

// round 14
// speedup vs baseline: 1.0458x; 1.0458x over previous
#include <cuda_runtime.h>
#include <cuda_fp16.h>
#include <stdint.h>

#define BATCH 4
#define SEQ   2048
#define DM    1024
#define NROW  (BATCH * SEQ)
typedef __half fp16;

// ---------------- scratch (__device__ globals; no allocation) ----------------
__device__ fp16 g_x16[(size_t)BATCH*SEQ*DM];      // x single fp16
__device__ fp16 g_wt[(size_t)3*DM*DM];            // W^T single fp16: [3*DM][DM]
__device__ float g_bias[3*DM];
__device__ fp16 g_qkv[(size_t)BATCH*SEQ*3*DM];    // [B*S][3DM]: q | k | v
__device__ fp16 g_vt[(size_t)BATCH*DM*SEQ];       // V^T
__device__ fp16 g_sp[(size_t)BATCH*SEQ*SEQ];      // unnormalized exp(scores), fp16
__device__ float g_rspart[(size_t)32*NROW];       // per-(bx,warp-n) row partial sums
__device__ float g_rinv[NROW];                    // 1 / rowsum

// ---------------- helpers ----------------
__device__ __forceinline__ uint32_t s2u(const void* p) {
    uint32_t a;
    asm("{ .reg .u64 t; cvta.to.shared.u64 t, %1; cvt.u32.u64 %0, t; }" : "=r"(a) : "l"(p));
    return a;
}
__device__ __forceinline__ void ldsm4(uint32_t* r, uint32_t addr) {
    asm volatile("ldmatrix.sync.aligned.m8n8.x4.shared.b16 {%0,%1,%2,%3}, [%4];"
                 : "=r"(r[0]), "=r"(r[1]), "=r"(r[2]), "=r"(r[3]) : "r"(addr));
}
__device__ __forceinline__ void mma16816(float* d, const uint32_t* a, uint32_t b0, uint32_t b1) {
    asm volatile(
        "mma.sync.aligned.m16n8k16.row.col.f32.f16.f16.f32 "
        "{%0,%1,%2,%3}, {%4,%5,%6,%7}, {%8,%9}, {%0,%1,%2,%3};"
        : "+f"(d[0]), "+f"(d[1]), "+f"(d[2]), "+f"(d[3])
        : "r"(a[0]), "r"(a[1]), "r"(a[2]), "r"(a[3]), "r"(b0), "r"(b1));
}

// ---------------- HMMA GEMM: C = op(A@B^T), single fp16 product ----------------
// Epilogue MODE (compile-time; no runtime branches in hot path):
//   0 (F16BIAS): Chi = fp16(acc + bias[n])
//   1 (EXP)    : Chi = fp16(exp(scale*acc)); deterministic row-partials -> rspart
//   2 (F32RINV): Cf  = acc * rinv[row]
// CTA 128x128, BK=64, 256 threads (8 warps, warp tile 32x64), 3 stages, 2 CTAs/SM.
#define BK      64
#define TILE_B  16384                    // 128 rows * 128B
#define NSTG    3
#define GSMEM   (NSTG * 2 * TILE_B)      // 96 KB

template<int MODE>
__global__ __launch_bounds__(256, 2) void gemmw(
    const fp16* __restrict__ A, const fp16* __restrict__ B,
    const float* __restrict__ bias, float scale,
    float* __restrict__ Cf, fp16* __restrict__ Chi,
    float* __restrict__ rspart, const float* __restrict__ rinv,
    int K, int lda, int ldb, int ldc,
    size_t sA, size_t sB, size_t sC)
{
    extern __shared__ char smem[];
    const uint32_t sb = s2u(smem);
    const int tid = threadIdx.x;
    const int wid = tid >> 5, lane = tid & 31;
    const int wm = wid & 3, wn = wid >> 2;           // warp grid 4 (m) x 2 (n)
    const int m0 = blockIdx.y * 128, n0 = blockIdx.x * 128;
    const int NC = K / BK;

    const fp16* bA = A + (size_t)blockIdx.z * sA + (size_t)m0 * lda;
    const fp16* bB = B + (size_t)blockIdx.z * sB + (size_t)n0 * ldb;

    auto load_chunk = [&](int c) {
        const uint32_t stg = sb + (uint32_t)(c % NSTG) * (2 * TILE_B);
        const int k0 = c * BK;
        #pragma unroll
        for (int i = 0; i < 8; i++) {
            const int t = i >> 2;                       // 0: A, 1: B
            const int sub = tid + (i & 3) * 256;        // 0..1023
            const int row = sub >> 3, col = sub & 7;    // 128 rows x 8 16B-cols
            const int ld = t ? ldb : lda;
            const fp16* src = (t ? bB : bA) + (size_t)row * ld + k0 + col * 8;
            uint32_t off = (uint32_t)(row * 128 + col * 16);
            uint32_t dst = stg + (uint32_t)t * TILE_B + (off ^ ((off >> 3) & 0x70));
            asm volatile("cp.async.cg.shared.global [%0], [%1], 16;" :: "r"(dst), "l"(src) : "memory");
        }
        asm volatile("cp.async.commit_group;" ::: "memory");
    };

    // per-lane ldmatrix addressing (SW128 rows of 128B)
    const int rlane = (lane & 7) + ((lane >> 3) & 1) * 8;
    const uint32_t xlane = (uint32_t)((rlane & 7) * 16);
    const uint32_t kbl = (uint32_t)((lane >> 4) * 16);
    uint32_t aoff[2], boff[4], kx[4];
    #pragma unroll
    for (int mf = 0; mf < 2; mf++) aoff[mf] = (uint32_t)((wm * 32 + mf * 16 + rlane) << 7);
    #pragma unroll
    for (int g = 0; g < 4; g++) boff[g] = (uint32_t)((wn * 64 + g * 16 + rlane) << 7);
    #pragma unroll
    for (int ks = 0; ks < 4; ks++) kx[ks] = ((uint32_t)(ks * 32) + kbl) ^ xlane;

    float acc[2][8][4] = {};

    load_chunk(0);
    if (NC > 1) load_chunk(1);

    for (int c = 0; c < NC; ++c) {
        if (c + 2 < NC) asm volatile("cp.async.wait_group 1;" ::: "memory");
        else            asm volatile("cp.async.wait_group 0;" ::: "memory");
        __syncthreads();                       // chunk c visible; oldest stage free
        if (c + 2 < NC) load_chunk(c + 2);

        const uint32_t stg = sb + (uint32_t)(c % NSTG) * (2 * TILE_B);
        const uint32_t sA_ = stg, sB_ = stg + TILE_B;

        #pragma unroll
        for (int ks = 0; ks < 4; ks++) {
            uint32_t ah[2][4], bf[8][2];
            ldsm4(ah[0], sA_ + aoff[0] + kx[ks]);
            ldsm4(ah[1], sA_ + aoff[1] + kx[ks]);
            #pragma unroll
            for (int g = 0; g < 4; g++) {
                uint32_t t[4];
                ldsm4(t, sB_ + boff[g] + kx[ks]);
                bf[2*g][0] = t[0]; bf[2*g+1][0] = t[1];
                bf[2*g][1] = t[2]; bf[2*g+1][1] = t[3];
            }
            #pragma unroll
            for (int mf = 0; mf < 2; mf++)
                #pragma unroll
                for (int nf = 0; nf < 8; nf++)
                    mma16816(acc[mf][nf], ah[mf], bf[nf][0], bf[nf][1]);
        }
    }

    // ---------------- epilogue (fully specialized per MODE) ----------------
    const size_t cb = (size_t)blockIdx.z * sC;

    if (MODE == 0) {                                   // fp16 out + bias (QKV)
        #pragma unroll
        for (int mf = 0; mf < 2; mf++) {
            const int m = m0 + wm * 32 + mf * 16 + (lane >> 2);
            #pragma unroll
            for (int nf = 0; nf < 8; nf++) {
                const int n = n0 + wn * 64 + nf * 8 + 2 * (lane & 3);
                const float b0 = bias[n], b1 = bias[n + 1];
                __half2 p0 = {__float2half(acc[mf][nf][0] + b0),
                              __float2half(acc[mf][nf][1] + b1)};
                __half2 p1 = {__float2half(acc[mf][nf][2] + b0),
                              __float2half(acc[mf][nf][3] + b1)};
                *reinterpret_cast<__half2*>(Chi + cb + (size_t)m * ldc + n)       = p0;
                *reinterpret_cast<__half2*>(Chi + cb + (size_t)(m + 8) * ldc + n) = p1;
            }
        }
    } else if (MODE == 1) {                            // exp + row partials (scores)
        float rs[2][2] = {};                           // [mf][row half]
        #pragma unroll
        for (int mf = 0; mf < 2; mf++) {
            const int m = m0 + wm * 32 + mf * 16 + (lane >> 2);
            #pragma unroll
            for (int nf = 0; nf < 8; nf++) {
                const int n = n0 + wn * 64 + nf * 8 + 2 * (lane & 3);
                float e00 = __expf(acc[mf][nf][0] * scale);
                float e01 = __expf(acc[mf][nf][1] * scale);
                float e10 = __expf(acc[mf][nf][2] * scale);
                float e11 = __expf(acc[mf][nf][3] * scale);
                rs[mf][0] += e00 + e01;
                rs[mf][1] += e10 + e11;
                __half2 p0 = {__float2half(e00), __float2half(e01)};
                __half2 p1 = {__float2half(e10), __float2half(e11)};
                *reinterpret_cast<__half2*>(Chi + cb + (size_t)m * ldc + n)       = p0;
                *reinterpret_cast<__half2*>(Chi + cb + (size_t)(m + 8) * ldc + n) = p1;
            }
        }
        #pragma unroll
        for (int o = 1; o < 4; o <<= 1) {
            #pragma unroll
            for (int mf = 0; mf < 2; mf++) {
                rs[mf][0] += __shfl_xor_sync(0xffffffffu, rs[mf][0], o);
                rs[mf][1] += __shfl_xor_sync(0xffffffffu, rs[mf][1], o);
            }
        }
        if ((lane & 3) == 0) {
            const int part = blockIdx.x * 2 + wn;
            #pragma unroll
            for (int mf = 0; mf < 2; mf++) {
                const int grow = blockIdx.z * SEQ + m0 + wm * 32 + mf * 16 + (lane >> 2);
                rspart[(size_t)part * NROW + grow]     = rs[mf][0];
                rspart[(size_t)part * NROW + grow + 8] = rs[mf][1];
            }
        }
    } else {                                           // fp32 out * rinv[row] (AV)
        #pragma unroll
        for (int mf = 0; mf < 2; mf++) {
            const int m = m0 + wm * 32 + mf * 16 + (lane >> 2);
            const float i0 = rinv[blockIdx.z * SEQ + m];
            const float i1 = rinv[blockIdx.z * SEQ + m + 8];
            #pragma unroll
            for (int nf = 0; nf < 8; nf++) {
                const int n = n0 + wn * 64 + nf * 8 + 2 * (lane & 3);
                float2 o0 = {acc[mf][nf][0] * i0, acc[mf][nf][1] * i0};
                float2 o1 = {acc[mf][nf][2] * i1, acc[mf][nf][3] * i1};
                *reinterpret_cast<float2*>(Cf + cb + (size_t)m * ldc + n)       = o0;
                *reinterpret_cast<float2*>(Cf + cb + (size_t)(m + 8) * ldc + n) = o1;
            }
        }
    }
}

// ---------------- aux kernels ----------------
__global__ __launch_bounds__(256) void conv_f16(const float* __restrict__ in,
                                                fp16* __restrict__ o, int n4)
{
    int i = blockIdx.x * 256 + threadIdx.x;
    if (i >= n4) return;
    float4 v = reinterpret_cast<const float4*>(in)[i];
    __align__(8) fp16 h[4];
    h[0] = __float2half(v.x); h[1] = __float2half(v.y);
    h[2] = __float2half(v.z); h[3] = __float2half(v.w);
    reinterpret_cast<uint2*>(o)[i] = *reinterpret_cast<uint2*>(h);
}

__global__ void concat_bias(const float* a, const float* b, const float* c, float* o)
{
    int i = blockIdx.x * 256 + threadIdx.x;
    if (i < DM)            o[i] = a[i];
    else if (i < 2 * DM)   o[i] = b[i - DM];
    else if (i < 3 * DM)   o[i] = c[i - 2 * DM];
}

// W [K=DM, N=DM] fp32 -> wt fp16 [N, K] (transposed), z selects Wq/Wk/Wv
__global__ void transpose_w_f16(const float* __restrict__ Wq, const float* __restrict__ Wk,
                                const float* __restrict__ Wv, fp16* __restrict__ wt)
{
    __shared__ float t[32][33];
    const float* W = blockIdx.z == 0 ? Wq : blockIdx.z == 1 ? Wk : Wv;
    fp16* o = wt + (size_t)blockIdx.z * DM * DM;
    const int n0 = blockIdx.x * 32, k0 = blockIdx.y * 32;
    const int tx = threadIdx.x, ty = threadIdx.y;
    #pragma unroll
    for (int r = 0; r < 4; r++)
        t[ty + 8 * r][tx] = W[(size_t)(k0 + ty + 8 * r) * DM + n0 + tx];
    __syncthreads();
    #pragma unroll
    for (int r = 0; r < 4; r++)
        o[(size_t)(n0 + ty + 8 * r) * DM + k0 + tx] = __float2half(t[tx][ty + 8 * r]);
}

// V slice of [B][SEQ][3*DM] (fp16, stride ldin) -> [B][DM][SEQ] fp16 transpose
__global__ void transpose_f16(const fp16* __restrict__ in, fp16* __restrict__ out, int ldin)
{
    __shared__ fp16 t[32][33];
    const size_t ib = (size_t)blockIdx.z * SEQ * ldin;
    const size_t ob = (size_t)blockIdx.z * DM * SEQ;
    const int s0 = blockIdx.y * 32, d0 = blockIdx.x * 32;
    const int tx = threadIdx.x, ty = threadIdx.y;
    #pragma unroll
    for (int r = 0; r < 4; r++)
        t[ty + 8 * r][tx] = in[ib + (size_t)(s0 + ty + 8 * r) * ldin + d0 + tx];
    __syncthreads();
    #pragma unroll
    for (int r = 0; r < 4; r++)
        out[ob + (size_t)(d0 + ty + 8 * r) * SEQ + s0 + tx] = t[tx][ty + 8 * r];
}

// sum 32 row-partials per row -> 1/rowsum (fixed order -> deterministic)
__global__ __launch_bounds__(256) void finalize_rsum(const float* __restrict__ part,
                                                     float* __restrict__ inv)
{
    int r = blockIdx.x * 256 + threadIdx.x;
    if (r >= NROW) return;
    float s = 0.f;
    #pragma unroll
    for (int p = 0; p < 32; p++) s += part[(size_t)p * NROW + r];
    inv[r] = 1.f / s;
}

// ---------------- launcher ----------------
extern "C" void kernel_launch(void* const* d_in, const int* in_sizes, int n_in,
                              void* d_out, int out_size)
{
    const float* x  = (const float*)d_in[0];
    const float* Wq = (const float*)d_in[1];
    const float* bq = (const float*)d_in[2];
    const float* Wk = (const float*)d_in[3];
    const float* bk = (const float*)d_in[4];
    const float* Wv = (const float*)d_in[5];
    const float* bv = (const float*)d_in[6];
    float* out = (float*)d_out;

    fp16 *x16, *wt, *qkv, *vt, *sp;
    float *bias, *rspart, *rinv;
    cudaGetSymbolAddress((void**)&x16, g_x16);
    cudaGetSymbolAddress((void**)&wt, g_wt);
    cudaGetSymbolAddress((void**)&qkv, g_qkv);
    cudaGetSymbolAddress((void**)&vt, g_vt);
    cudaGetSymbolAddress((void**)&sp, g_sp);
    cudaGetSymbolAddress((void**)&bias, g_bias);
    cudaGetSymbolAddress((void**)&rspart, g_rspart);
    cudaGetSymbolAddress((void**)&rinv, g_rinv);

    cudaFuncSetAttribute(gemmw<0>, cudaFuncAttributeMaxDynamicSharedMemorySize, GSMEM);
    cudaFuncSetAttribute(gemmw<1>, cudaFuncAttributeMaxDynamicSharedMemorySize, GSMEM);
    cudaFuncSetAttribute(gemmw<2>, cudaFuncAttributeMaxDynamicSharedMemorySize, GSMEM);

    const int M = BATCH * SEQ;

    // 1. convert x; transpose W; concat bias
    conv_f16<<<(M * DM / 4 + 255) / 256, 256>>>(x, x16, M * DM / 4);
    transpose_w_f16<<<dim3(DM / 32, DM / 32, 3), dim3(32, 8)>>>(Wq, Wk, Wv, wt);
    concat_bias<<<(3 * DM + 255) / 256, 256>>>(bq, bk, bv, bias);

    // 2. fused QKV projection: [8192, 3072] = x16 @ wt^T + bias
    gemmw<0><<<dim3(3 * DM / 128, M / 128, 1), 256, GSMEM>>>(
        x16, wt, bias, 1.f,
        nullptr, qkv, nullptr, nullptr,
        DM, DM, DM, 3 * DM, 0, 0, 0);

    // 3. V^T
    transpose_f16<<<dim3(DM / 32, SEQ / 32, BATCH), dim3(32, 8)>>>(qkv + 2 * DM, vt, 3 * DM);

    // 4. exp(scale * Q @ K^T) -> fp16 (unnormalized) + row-partial sums
    gemmw<1><<<dim3(SEQ / 128, SEQ / 128, BATCH), 256, GSMEM>>>(
        qkv, qkv + DM, nullptr, 0.03125f,
        nullptr, sp, rspart, nullptr,
        DM, 3 * DM, 3 * DM, SEQ,
        (size_t)SEQ * 3 * DM, (size_t)SEQ * 3 * DM, (size_t)SEQ * SEQ);

    // 5. 1/rowsum
    finalize_rsum<<<(NROW + 255) / 256, 256>>>(rspart, rinv);

    // 6. out = (exp @ V) * rinv[row]
    gemmw<2><<<dim3(DM / 128, SEQ / 128, BATCH), 256, GSMEM>>>(
        sp, vt, nullptr, 1.f,
        out, nullptr, nullptr, rinv,
        SEQ, SEQ, SEQ, DM,
        (size_t)SEQ * SEQ, (size_t)DM * SEQ, (size_t)SEQ * DM);
}

// round 15
// speedup vs baseline: 1.0979x; 1.0498x over previous
#include <cuda_runtime.h>
#include <cuda_fp16.h>
#include <stdint.h>

#define BATCH 4
#define SEQ   2048
#define DM    1024
#define NROW  (BATCH * SEQ)
typedef __half fp16;

// ---------------- scratch (__device__ globals; no allocation) ----------------
__device__ fp16 g_x16[(size_t)BATCH*SEQ*DM];      // x single fp16
__device__ fp16 g_wt[(size_t)3*DM*DM];            // W^T single fp16: [3*DM][DM]
__device__ float g_bias[3*DM];
__device__ fp16 g_qkv[(size_t)BATCH*SEQ*3*DM];    // [B*S][3DM]: q | k | v
__device__ fp16 g_sp[(size_t)BATCH*SEQ*SEQ];      // unnormalized exp(scores), fp16
__device__ float g_rspart[(size_t)32*NROW];       // per-(bx,warp-n) row partial sums
__device__ float g_rinv[NROW];                    // 1 / rowsum

// ---------------- helpers ----------------
__device__ __forceinline__ uint32_t s2u(const void* p) {
    uint32_t a;
    asm("{ .reg .u64 t; cvta.to.shared.u64 t, %1; cvt.u32.u64 %0, t; }" : "=r"(a) : "l"(p));
    return a;
}
__device__ __forceinline__ void ldsm4(uint32_t* r, uint32_t addr) {
    asm volatile("ldmatrix.sync.aligned.m8n8.x4.shared.b16 {%0,%1,%2,%3}, [%4];"
                 : "=r"(r[0]), "=r"(r[1]), "=r"(r[2]), "=r"(r[3]) : "r"(addr));
}
__device__ __forceinline__ void ldsm4t(uint32_t* r, uint32_t addr) {
    asm volatile("ldmatrix.sync.aligned.m8n8.x4.trans.shared.b16 {%0,%1,%2,%3}, [%4];"
                 : "=r"(r[0]), "=r"(r[1]), "=r"(r[2]), "=r"(r[3]) : "r"(addr));
}
__device__ __forceinline__ void mma16816(float* d, const uint32_t* a, uint32_t b0, uint32_t b1) {
    asm volatile(
        "mma.sync.aligned.m16n8k16.row.col.f32.f16.f16.f32 "
        "{%0,%1,%2,%3}, {%4,%5,%6,%7}, {%8,%9}, {%0,%1,%2,%3};"
        : "+f"(d[0]), "+f"(d[1]), "+f"(d[2]), "+f"(d[3])
        : "r"(a[0]), "r"(a[1]), "r"(a[2]), "r"(a[3]), "r"(b0), "r"(b1));
}

#define BK      64
#define TILE_B  16384                    // 16 KB per operand tile
#define NSTG    3
#define GSMEM   (NSTG * 2 * TILE_B)      // 96 KB

// ---------------- gemmw: C = op(A@B^T); A,B K-major. MODE 0: fp16+bias. MODE 1: exp+partials.
template<int MODE>
__global__ __launch_bounds__(256, 2) void gemmw(
    const fp16* __restrict__ A, const fp16* __restrict__ B,
    const float* __restrict__ bias, float scale,
    fp16* __restrict__ Chi, float* __restrict__ rspart,
    int K, int lda, int ldb, int ldc,
    size_t sA, size_t sB, size_t sC)
{
    extern __shared__ char smem[];
    const uint32_t sb = s2u(smem);
    const int tid = threadIdx.x;
    const int wid = tid >> 5, lane = tid & 31;
    const int wm = wid & 3, wn = wid >> 2;           // warp grid 4 (m) x 2 (n)
    const int m0 = blockIdx.y * 128, n0 = blockIdx.x * 128;
    const int NC = K / BK;

    const fp16* bA = A + (size_t)blockIdx.z * sA + (size_t)m0 * lda;
    const fp16* bB = B + (size_t)blockIdx.z * sB + (size_t)n0 * ldb;

    auto load_chunk = [&](int c) {
        const uint32_t stg = sb + (uint32_t)(c % NSTG) * (2 * TILE_B);
        const int k0 = c * BK;
        #pragma unroll
        for (int i = 0; i < 8; i++) {
            const int t = i >> 2;                       // 0: A, 1: B
            const int sub = tid + (i & 3) * 256;
            const int row = sub >> 3, col = sub & 7;    // 128 rows x 8 16B-cols
            const int ld = t ? ldb : lda;
            const fp16* src = (t ? bB : bA) + (size_t)row * ld + k0 + col * 8;
            uint32_t off = (uint32_t)(row * 128 + col * 16);
            uint32_t dst = stg + (uint32_t)t * TILE_B + (off ^ ((off >> 3) & 0x70));
            asm volatile("cp.async.cg.shared.global [%0], [%1], 16;" :: "r"(dst), "l"(src) : "memory");
        }
        asm volatile("cp.async.commit_group;" ::: "memory");
    };

    const int rlane = (lane & 7) + ((lane >> 3) & 1) * 8;
    const uint32_t xlane = (uint32_t)((rlane & 7) * 16);
    const uint32_t kbl = (uint32_t)((lane >> 4) * 16);
    uint32_t aoff[2], boff[4], kx[4];
    #pragma unroll
    for (int mf = 0; mf < 2; mf++) aoff[mf] = (uint32_t)((wm * 32 + mf * 16 + rlane) << 7);
    #pragma unroll
    for (int g = 0; g < 4; g++) boff[g] = (uint32_t)((wn * 64 + g * 16 + rlane) << 7);
    #pragma unroll
    for (int ks = 0; ks < 4; ks++) kx[ks] = ((uint32_t)(ks * 32) + kbl) ^ xlane;

    float acc[2][8][4] = {};

    load_chunk(0);
    if (NC > 1) load_chunk(1);

    for (int c = 0; c < NC; ++c) {
        if (c + 2 < NC) asm volatile("cp.async.wait_group 1;" ::: "memory");
        else            asm volatile("cp.async.wait_group 0;" ::: "memory");
        __syncthreads();
        if (c + 2 < NC) load_chunk(c + 2);

        const uint32_t stg = sb + (uint32_t)(c % NSTG) * (2 * TILE_B);
        const uint32_t sA_ = stg, sB_ = stg + TILE_B;

        #pragma unroll
        for (int ks = 0; ks < 4; ks++) {
            uint32_t ah[2][4], bf[8][2];
            ldsm4(ah[0], sA_ + aoff[0] + kx[ks]);
            ldsm4(ah[1], sA_ + aoff[1] + kx[ks]);
            #pragma unroll
            for (int g = 0; g < 4; g++) {
                uint32_t t[4];
                ldsm4(t, sB_ + boff[g] + kx[ks]);
                bf[2*g][0] = t[0]; bf[2*g+1][0] = t[1];
                bf[2*g][1] = t[2]; bf[2*g+1][1] = t[3];
            }
            #pragma unroll
            for (int mf = 0; mf < 2; mf++)
                #pragma unroll
                for (int nf = 0; nf < 8; nf++)
                    mma16816(acc[mf][nf], ah[mf], bf[nf][0], bf[nf][1]);
        }
    }

    const size_t cb = (size_t)blockIdx.z * sC;
    if (MODE == 0) {                                   // fp16 out + bias (QKV)
        #pragma unroll
        for (int mf = 0; mf < 2; mf++) {
            const int m = m0 + wm * 32 + mf * 16 + (lane >> 2);
            #pragma unroll
            for (int nf = 0; nf < 8; nf++) {
                const int n = n0 + wn * 64 + nf * 8 + 2 * (lane & 3);
                const float b0 = bias[n], b1 = bias[n + 1];
                __half2 p0 = {__float2half(acc[mf][nf][0] + b0),
                              __float2half(acc[mf][nf][1] + b1)};
                __half2 p1 = {__float2half(acc[mf][nf][2] + b0),
                              __float2half(acc[mf][nf][3] + b1)};
                *reinterpret_cast<__half2*>(Chi + cb + (size_t)m * ldc + n)       = p0;
                *reinterpret_cast<__half2*>(Chi + cb + (size_t)(m + 8) * ldc + n) = p1;
            }
        }
    } else {                                           // exp + row partials (scores)
        float rs[2][2] = {};
        #pragma unroll
        for (int mf = 0; mf < 2; mf++) {
            const int m = m0 + wm * 32 + mf * 16 + (lane >> 2);
            #pragma unroll
            for (int nf = 0; nf < 8; nf++) {
                const int n = n0 + wn * 64 + nf * 8 + 2 * (lane & 3);
                float e00 = __expf(acc[mf][nf][0] * scale);
                float e01 = __expf(acc[mf][nf][1] * scale);
                float e10 = __expf(acc[mf][nf][2] * scale);
                float e11 = __expf(acc[mf][nf][3] * scale);
                rs[mf][0] += e00 + e01;
                rs[mf][1] += e10 + e11;
                __half2 p0 = {__float2half(e00), __float2half(e01)};
                __half2 p1 = {__float2half(e10), __float2half(e11)};
                *reinterpret_cast<__half2*>(Chi + cb + (size_t)m * ldc + n)       = p0;
                *reinterpret_cast<__half2*>(Chi + cb + (size_t)(m + 8) * ldc + n) = p1;
            }
        }
        #pragma unroll
        for (int o = 1; o < 4; o <<= 1) {
            #pragma unroll
            for (int mf = 0; mf < 2; mf++) {
                rs[mf][0] += __shfl_xor_sync(0xffffffffu, rs[mf][0], o);
                rs[mf][1] += __shfl_xor_sync(0xffffffffu, rs[mf][1], o);
            }
        }
        if ((lane & 3) == 0) {
            const int part = blockIdx.x * 2 + wn;
            #pragma unroll
            for (int mf = 0; mf < 2; mf++) {
                const int grow = blockIdx.z * SEQ + m0 + wm * 32 + mf * 16 + (lane >> 2);
                rspart[(size_t)part * NROW + grow]     = rs[mf][0];
                rspart[(size_t)part * NROW + grow + 8] = rs[mf][1];
            }
        }
    }
}

// ---------------- gemmv: out[m,n] = (Σ_t A[m,t]·V[t,n]) * rinv[m]; V consumed natively
// A [M,K] K-major (stride lda). V rows t (stride ldb), columns n (+n0 offset).
// B smem tile: 64 t-rows x 256B, chunk^=(row&7) swizzle; B-frags via ldmatrix.x4.trans.
__global__ __launch_bounds__(256, 2) void gemmv(
    const fp16* __restrict__ A, const fp16* __restrict__ V,
    const float* __restrict__ rinv, float* __restrict__ Cf,
    int K, int lda, int ldb, int ldc,
    size_t sA, size_t sB, size_t sC)
{
    extern __shared__ char smem[];
    const uint32_t sb = s2u(smem);
    const int tid = threadIdx.x;
    const int wid = tid >> 5, lane = tid & 31;
    const int wm = wid & 3, wn = wid >> 2;
    const int m0 = blockIdx.y * 128, n0 = blockIdx.x * 128;
    const int NC = K / BK;

    const fp16* bA = A + (size_t)blockIdx.z * sA + (size_t)m0 * lda;
    const fp16* bB = V + (size_t)blockIdx.z * sB + n0;          // column offset!

    auto load_chunk = [&](int c) {
        const uint32_t stg = sb + (uint32_t)(c % NSTG) * (2 * TILE_B);
        const int k0 = c * BK;
        #pragma unroll
        for (int i = 0; i < 4; i++) {                   // A tile: 128 rows x 128B
            const int sub = tid + i * 256;
            const int row = sub >> 3, col = sub & 7;
            const fp16* src = bA + (size_t)row * lda + k0 + col * 8;
            uint32_t off = (uint32_t)(row * 128 + col * 16);
            uint32_t dst = stg + (off ^ ((off >> 3) & 0x70));
            asm volatile("cp.async.cg.shared.global [%0], [%1], 16;" :: "r"(dst), "l"(src) : "memory");
        }
        #pragma unroll
        for (int i = 0; i < 4; i++) {                   // V tile: 64 t-rows x 256B
            const int sub = tid + i * 256;
            const int row = sub >> 4, col = sub & 15;
            const fp16* src = bB + (size_t)(k0 + row) * ldb + col * 8;
            uint32_t dst = stg + TILE_B + (uint32_t)(row * 256)
                         + ((uint32_t)(col ^ (row & 7)) << 4);
            asm volatile("cp.async.cg.shared.global [%0], [%1], 16;" :: "r"(dst), "l"(src) : "memory");
        }
        asm volatile("cp.async.commit_group;" ::: "memory");
    };

    const int rlane = (lane & 7) + ((lane >> 3) & 1) * 8;
    const uint32_t xlane = (uint32_t)((rlane & 7) * 16);
    const uint32_t kbl = (uint32_t)((lane >> 4) * 16);
    const uint32_t x7 = (uint32_t)(rlane & 7);
    const uint32_t nch = (uint32_t)((lane >> 4) & 1);
    uint32_t aoff[2], boffT[4], kx[4];
    #pragma unroll
    for (int mf = 0; mf < 2; mf++) aoff[mf] = (uint32_t)((wm * 32 + mf * 16 + rlane) << 7);
    #pragma unroll
    for (int g = 0; g < 4; g++)
        boffT[g] = (uint32_t)(rlane * 256)
                 + ((((uint32_t)(wn * 8 + g * 2) + nch) ^ x7) << 4);
    #pragma unroll
    for (int ks = 0; ks < 4; ks++) kx[ks] = ((uint32_t)(ks * 32) + kbl) ^ xlane;

    float acc[2][8][4] = {};

    load_chunk(0);
    if (NC > 1) load_chunk(1);

    for (int c = 0; c < NC; ++c) {
        if (c + 2 < NC) asm volatile("cp.async.wait_group 1;" ::: "memory");
        else            asm volatile("cp.async.wait_group 0;" ::: "memory");
        __syncthreads();
        if (c + 2 < NC) load_chunk(c + 2);

        const uint32_t stg = sb + (uint32_t)(c % NSTG) * (2 * TILE_B);
        const uint32_t sA_ = stg, sB_ = stg + TILE_B;

        #pragma unroll
        for (int ks = 0; ks < 4; ks++) {
            uint32_t ah[2][4], bf[8][2];
            ldsm4(ah[0], sA_ + aoff[0] + kx[ks]);
            ldsm4(ah[1], sA_ + aoff[1] + kx[ks]);
            #pragma unroll
            for (int g = 0; g < 4; g++) {
                uint32_t t[4];
                ldsm4t(t, sB_ + (uint32_t)(ks * 4096) + boffT[g]);
                bf[2*g][0]   = t[0]; bf[2*g][1]   = t[1];   // n-lo: k0-7, k8-15
                bf[2*g+1][0] = t[2]; bf[2*g+1][1] = t[3];   // n-hi
            }
            #pragma unroll
            for (int mf = 0; mf < 2; mf++)
                #pragma unroll
                for (int nf = 0; nf < 8; nf++)
                    mma16816(acc[mf][nf], ah[mf], bf[nf][0], bf[nf][1]);
        }
    }

    const size_t cb = (size_t)blockIdx.z * sC;
    #pragma unroll
    for (int mf = 0; mf < 2; mf++) {
        const int m = m0 + wm * 32 + mf * 16 + (lane >> 2);
        const float i0 = rinv[blockIdx.z * SEQ + m];
        const float i1 = rinv[blockIdx.z * SEQ + m + 8];
        #pragma unroll
        for (int nf = 0; nf < 8; nf++) {
            const int n = n0 + wn * 64 + nf * 8 + 2 * (lane & 3);
            float2 o0 = {acc[mf][nf][0] * i0, acc[mf][nf][1] * i0};
            float2 o1 = {acc[mf][nf][2] * i1, acc[mf][nf][3] * i1};
            *reinterpret_cast<float2*>(Cf + cb + (size_t)m * ldc + n)       = o0;
            *reinterpret_cast<float2*>(Cf + cb + (size_t)(m + 8) * ldc + n) = o1;
        }
    }
}

// ---------------- aux kernels ----------------
__global__ __launch_bounds__(256) void conv_f16(const float* __restrict__ in,
                                                fp16* __restrict__ o, int n4)
{
    int i = blockIdx.x * 256 + threadIdx.x;
    if (i >= n4) return;
    float4 v = reinterpret_cast<const float4*>(in)[i];
    __align__(8) fp16 h[4];
    h[0] = __float2half(v.x); h[1] = __float2half(v.y);
    h[2] = __float2half(v.z); h[3] = __float2half(v.w);
    reinterpret_cast<uint2*>(o)[i] = *reinterpret_cast<uint2*>(h);
}

// W -> W^T fp16, and block (0,0,z) also copies its bias third into g-bias
__global__ void transpose_w_f16(const float* __restrict__ Wq, const float* __restrict__ Wk,
                                const float* __restrict__ Wv,
                                const float* __restrict__ bq, const float* __restrict__ bk,
                                const float* __restrict__ bv,
                                fp16* __restrict__ wt, float* __restrict__ bias)
{
    __shared__ float t[32][33];
    const float* W = blockIdx.z == 0 ? Wq : blockIdx.z == 1 ? Wk : Wv;
    fp16* o = wt + (size_t)blockIdx.z * DM * DM;
    const int n0 = blockIdx.x * 32, k0 = blockIdx.y * 32;
    const int tx = threadIdx.x, ty = threadIdx.y;
    if (blockIdx.x == 0 && blockIdx.y == 0) {
        const float* b = blockIdx.z == 0 ? bq : blockIdx.z == 1 ? bk : bv;
        const int tid = ty * 32 + tx;
        #pragma unroll
        for (int j = 0; j < 4; j++)
            bias[blockIdx.z * DM + tid + j * 256] = b[tid + j * 256];
    }
    #pragma unroll
    for (int r = 0; r < 4; r++)
        t[ty + 8 * r][tx] = W[(size_t)(k0 + ty + 8 * r) * DM + n0 + tx];
    __syncthreads();
    #pragma unroll
    for (int r = 0; r < 4; r++)
        o[(size_t)(n0 + ty + 8 * r) * DM + k0 + tx] = __float2half(t[tx][ty + 8 * r]);
}

// sum 32 row-partials per row -> 1/rowsum (fixed order -> deterministic)
__global__ __launch_bounds__(256) void finalize_rsum(const float* __restrict__ part,
                                                     float* __restrict__ inv)
{
    int r = blockIdx.x * 256 + threadIdx.x;
    if (r >= NROW) return;
    float s = 0.f;
    #pragma unroll
    for (int p = 0; p < 32; p++) s += part[(size_t)p * NROW + r];
    inv[r] = 1.f / s;
}

// ---------------- launcher ----------------
extern "C" void kernel_launch(void* const* d_in, const int* in_sizes, int n_in,
                              void* d_out, int out_size)
{
    const float* x  = (const float*)d_in[0];
    const float* Wq = (const float*)d_in[1];
    const float* bq = (const float*)d_in[2];
    const float* Wk = (const float*)d_in[3];
    const float* bk = (const float*)d_in[4];
    const float* Wv = (const float*)d_in[5];
    const float* bv = (const float*)d_in[6];
    float* out = (float*)d_out;

    fp16 *x16, *wt, *qkv, *sp;
    float *bias, *rspart, *rinv;
    cudaGetSymbolAddress((void**)&x16, g_x16);
    cudaGetSymbolAddress((void**)&wt, g_wt);
    cudaGetSymbolAddress((void**)&qkv, g_qkv);
    cudaGetSymbolAddress((void**)&sp, g_sp);
    cudaGetSymbolAddress((void**)&bias, g_bias);
    cudaGetSymbolAddress((void**)&rspart, g_rspart);
    cudaGetSymbolAddress((void**)&rinv, g_rinv);

    cudaFuncSetAttribute(gemmw<0>, cudaFuncAttributeMaxDynamicSharedMemorySize, GSMEM);
    cudaFuncSetAttribute(gemmw<1>, cudaFuncAttributeMaxDynamicSharedMemorySize, GSMEM);
    cudaFuncSetAttribute(gemmv,    cudaFuncAttributeMaxDynamicSharedMemorySize, GSMEM);

    const int M = BATCH * SEQ;

    // 1. convert x; transpose W (+fused bias concat)
    conv_f16<<<(M * DM / 4 + 255) / 256, 256>>>(x, x16, M * DM / 4);
    transpose_w_f16<<<dim3(DM / 32, DM / 32, 3), dim3(32, 8)>>>(
        Wq, Wk, Wv, bq, bk, bv, wt, bias);

    // 2. fused QKV projection: [8192, 3072] = x16 @ wt^T + bias
    gemmw<0><<<dim3(3 * DM / 128, M / 128, 1), 256, GSMEM>>>(
        x16, wt, bias, 1.f, qkv, nullptr,
        DM, DM, DM, 3 * DM, 0, 0, 0);

    // 3. exp(scale * Q @ K^T) -> fp16 (unnormalized) + row-partial sums
    gemmw<1><<<dim3(SEQ / 128, SEQ / 128, BATCH), 256, GSMEM>>>(
        qkv, qkv + DM, nullptr, 0.03125f, sp, rspart,
        DM, 3 * DM, 3 * DM, SEQ,
        (size_t)SEQ * 3 * DM, (size_t)SEQ * 3 * DM, (size_t)SEQ * SEQ);

    // 4. 1/rowsum
    finalize_rsum<<<(NROW + 255) / 256, 256>>>(rspart, rinv);

    // 5. out = (exp @ V) * rinv[row]; V consumed natively via ldmatrix.trans
    gemmv<<<dim3(DM / 128, SEQ / 128, BATCH), 256, GSMEM>>>(
        sp, qkv + 2 * DM, rinv, out,
        SEQ, SEQ, 3 * DM, DM,
        (size_t)SEQ * SEQ, (size_t)SEQ * 3 * DM, (size_t)SEQ * DM);
}

// round 16
// speedup vs baseline: 1.1166x; 1.0171x over previous
#include <cuda_runtime.h>
#include <cuda_fp16.h>
#include <stdint.h>

#define BATCH 4
#define SEQ   2048
#define DM    1024
#define NROW  (BATCH * SEQ)
typedef __half fp16;

// ---------------- scratch (__device__ globals; no allocation) ----------------
__device__ fp16 g_x16[(size_t)BATCH*SEQ*DM];      // x single fp16
__device__ fp16 g_wt[(size_t)3*DM*DM];            // W^T single fp16: [3*DM][DM]
__device__ float g_bias[3*DM];
__device__ fp16 g_qkv[(size_t)BATCH*SEQ*3*DM];    // [B*S][3DM]: q | k | v
__device__ fp16 g_sp[(size_t)BATCH*SEQ*SEQ];      // unnormalized exp(scores), fp16
__device__ float g_rspart[(size_t)32*NROW];       // per-(bx,warp-n) row partial sums

// ---------------- helpers ----------------
__device__ __forceinline__ uint32_t s2u(const void* p) {
    uint32_t a;
    asm("{ .reg .u64 t; cvta.to.shared.u64 t, %1; cvt.u32.u64 %0, t; }" : "=r"(a) : "l"(p));
    return a;
}
__device__ __forceinline__ void ldsm4(uint32_t* r, uint32_t addr) {
    asm volatile("ldmatrix.sync.aligned.m8n8.x4.shared.b16 {%0,%1,%2,%3}, [%4];"
                 : "=r"(r[0]), "=r"(r[1]), "=r"(r[2]), "=r"(r[3]) : "r"(addr));
}
__device__ __forceinline__ void ldsm4t(uint32_t* r, uint32_t addr) {
    asm volatile("ldmatrix.sync.aligned.m8n8.x4.trans.shared.b16 {%0,%1,%2,%3}, [%4];"
                 : "=r"(r[0]), "=r"(r[1]), "=r"(r[2]), "=r"(r[3]) : "r"(addr));
}
__device__ __forceinline__ void mma16816(float* d, const uint32_t* a, uint32_t b0, uint32_t b1) {
    asm volatile(
        "mma.sync.aligned.m16n8k16.row.col.f32.f16.f16.f32 "
        "{%0,%1,%2,%3}, {%4,%5,%6,%7}, {%8,%9}, {%0,%1,%2,%3};"
        : "+f"(d[0]), "+f"(d[1]), "+f"(d[2]), "+f"(d[3])
        : "r"(a[0]), "r"(a[1]), "r"(a[2]), "r"(a[3]), "r"(b0), "r"(b1));
}

#define BK      64
#define TILE_B  16384                    // 16 KB per operand tile
#define NSTG    3
#define GSMEM   (NSTG * 2 * TILE_B)      // 96 KB
#define VSMEM   (GSMEM + 512)            // gemmv: + smem rinv[128]

// ---------------- gemmw: C = op(A@B^T); A,B K-major. MODE 0: fp16+bias. MODE 1: exp+partials.
template<int MODE>
__global__ __launch_bounds__(256, 2) void gemmw(
    const fp16* __restrict__ A, const fp16* __restrict__ B,
    const float* __restrict__ bias, float scale,
    fp16* __restrict__ Chi, float* __restrict__ rspart,
    int K, int lda, int ldb, int ldc,
    size_t sA, size_t sB, size_t sC)
{
    extern __shared__ char smem[];
    const uint32_t sb = s2u(smem);
    const int tid = threadIdx.x;
    const int wid = tid >> 5, lane = tid & 31;
    const int wm = wid & 3, wn = wid >> 2;           // warp grid 4 (m) x 2 (n)
    const int m0 = blockIdx.y * 128, n0 = blockIdx.x * 128;
    const int NC = K / BK;

    const fp16* bA = A + (size_t)blockIdx.z * sA + (size_t)m0 * lda;
    const fp16* bB = B + (size_t)blockIdx.z * sB + (size_t)n0 * ldb;

    auto load_chunk = [&](int c) {
        const uint32_t stg = sb + (uint32_t)(c % NSTG) * (2 * TILE_B);
        const int k0 = c * BK;
        #pragma unroll
        for (int i = 0; i < 8; i++) {
            const int t = i >> 2;                       // 0: A, 1: B
            const int sub = tid + (i & 3) * 256;
            const int row = sub >> 3, col = sub & 7;    // 128 rows x 8 16B-cols
            const int ld = t ? ldb : lda;
            const fp16* src = (t ? bB : bA) + (size_t)row * ld + k0 + col * 8;
            uint32_t off = (uint32_t)(row * 128 + col * 16);
            uint32_t dst = stg + (uint32_t)t * TILE_B + (off ^ ((off >> 3) & 0x70));
            asm volatile("cp.async.cg.shared.global [%0], [%1], 16;" :: "r"(dst), "l"(src) : "memory");
        }
        asm volatile("cp.async.commit_group;" ::: "memory");
    };

    const int rlane = (lane & 7) + ((lane >> 3) & 1) * 8;
    const uint32_t xlane = (uint32_t)((rlane & 7) * 16);
    const uint32_t kbl = (uint32_t)((lane >> 4) * 16);
    uint32_t aoff[2], boff[4], kx[4];
    #pragma unroll
    for (int mf = 0; mf < 2; mf++) aoff[mf] = (uint32_t)((wm * 32 + mf * 16 + rlane) << 7);
    #pragma unroll
    for (int g = 0; g < 4; g++) boff[g] = (uint32_t)((wn * 64 + g * 16 + rlane) << 7);
    #pragma unroll
    for (int ks = 0; ks < 4; ks++) kx[ks] = ((uint32_t)(ks * 32) + kbl) ^ xlane;

    float acc[2][8][4] = {};

    load_chunk(0);
    if (NC > 1) load_chunk(1);

    for (int c = 0; c < NC; ++c) {
        if (c + 2 < NC) asm volatile("cp.async.wait_group 1;" ::: "memory");
        else            asm volatile("cp.async.wait_group 0;" ::: "memory");
        __syncthreads();
        if (c + 2 < NC) load_chunk(c + 2);

        const uint32_t stg = sb + (uint32_t)(c % NSTG) * (2 * TILE_B);
        const uint32_t sA_ = stg, sB_ = stg + TILE_B;

        #pragma unroll
        for (int ks = 0; ks < 4; ks++) {
            uint32_t ah[2][4], bf[8][2];
            ldsm4(ah[0], sA_ + aoff[0] + kx[ks]);
            ldsm4(ah[1], sA_ + aoff[1] + kx[ks]);
            #pragma unroll
            for (int g = 0; g < 4; g++) {
                uint32_t t[4];
                ldsm4(t, sB_ + boff[g] + kx[ks]);
                bf[2*g][0] = t[0]; bf[2*g+1][0] = t[1];
                bf[2*g][1] = t[2]; bf[2*g+1][1] = t[3];
            }
            #pragma unroll
            for (int mf = 0; mf < 2; mf++)
                #pragma unroll
                for (int nf = 0; nf < 8; nf++)
                    mma16816(acc[mf][nf], ah[mf], bf[nf][0], bf[nf][1]);
        }
    }

    const size_t cb = (size_t)blockIdx.z * sC;
    if (MODE == 0) {                                   // fp16 out + bias (QKV)
        #pragma unroll
        for (int mf = 0; mf < 2; mf++) {
            const int m = m0 + wm * 32 + mf * 16 + (lane >> 2);
            #pragma unroll
            for (int nf = 0; nf < 8; nf++) {
                const int n = n0 + wn * 64 + nf * 8 + 2 * (lane & 3);
                const float b0 = bias[n], b1 = bias[n + 1];
                __half2 p0 = {__float2half(acc[mf][nf][0] + b0),
                              __float2half(acc[mf][nf][1] + b1)};
                __half2 p1 = {__float2half(acc[mf][nf][2] + b0),
                              __float2half(acc[mf][nf][3] + b1)};
                *reinterpret_cast<__half2*>(Chi + cb + (size_t)m * ldc + n)       = p0;
                *reinterpret_cast<__half2*>(Chi + cb + (size_t)(m + 8) * ldc + n) = p1;
            }
        }
    } else {                                           // exp + row partials (scores)
        float rs[2][2] = {};
        #pragma unroll
        for (int mf = 0; mf < 2; mf++) {
            const int m = m0 + wm * 32 + mf * 16 + (lane >> 2);
            #pragma unroll
            for (int nf = 0; nf < 8; nf++) {
                const int n = n0 + wn * 64 + nf * 8 + 2 * (lane & 3);
                float e00 = __expf(acc[mf][nf][0] * scale);
                float e01 = __expf(acc[mf][nf][1] * scale);
                float e10 = __expf(acc[mf][nf][2] * scale);
                float e11 = __expf(acc[mf][nf][3] * scale);
                rs[mf][0] += e00 + e01;
                rs[mf][1] += e10 + e11;
                __half2 p0 = {__float2half(e00), __float2half(e01)};
                __half2 p1 = {__float2half(e10), __float2half(e11)};
                *reinterpret_cast<__half2*>(Chi + cb + (size_t)m * ldc + n)       = p0;
                *reinterpret_cast<__half2*>(Chi + cb + (size_t)(m + 8) * ldc + n) = p1;
            }
        }
        #pragma unroll
        for (int o = 1; o < 4; o <<= 1) {
            #pragma unroll
            for (int mf = 0; mf < 2; mf++) {
                rs[mf][0] += __shfl_xor_sync(0xffffffffu, rs[mf][0], o);
                rs[mf][1] += __shfl_xor_sync(0xffffffffu, rs[mf][1], o);
            }
        }
        if ((lane & 3) == 0) {
            const int part = blockIdx.x * 2 + wn;
            #pragma unroll
            for (int mf = 0; mf < 2; mf++) {
                const int grow = blockIdx.z * SEQ + m0 + wm * 32 + mf * 16 + (lane >> 2);
                rspart[(size_t)part * NROW + grow]     = rs[mf][0];
                rspart[(size_t)part * NROW + grow + 8] = rs[mf][1];
            }
        }
    }
}

// ---------------- gemmv: out[m,n] = (Σ_t A[m,t]·V[t,n]) * rinv[m]; V native, rinv in prologue
__global__ __launch_bounds__(256, 2) void gemmv(
    const fp16* __restrict__ A, const fp16* __restrict__ V,
    const float* __restrict__ rspart, float* __restrict__ Cf,
    int K, int lda, int ldb, int ldc,
    size_t sA, size_t sB, size_t sC)
{
    extern __shared__ char smem[];
    const uint32_t sb = s2u(smem);
    float* srinv = reinterpret_cast<float*>(smem + GSMEM);   // 128 floats
    const int tid = threadIdx.x;
    const int wid = tid >> 5, lane = tid & 31;
    const int wm = wid & 3, wn = wid >> 2;
    const int m0 = blockIdx.y * 128, n0 = blockIdx.x * 128;
    const int NC = K / BK;

    // prologue: rinv for this CTA's 128 rows (same summation order as old finalize)
    if (tid < 128) {
        const int grow = blockIdx.z * SEQ + m0 + tid;
        float s = 0.f;
        #pragma unroll
        for (int p = 0; p < 32; p++) s += rspart[(size_t)p * NROW + grow];
        srinv[tid] = 1.f / s;
    }

    const fp16* bA = A + (size_t)blockIdx.z * sA + (size_t)m0 * lda;
    const fp16* bB = V + (size_t)blockIdx.z * sB + n0;          // column offset!

    auto load_chunk = [&](int c) {
        const uint32_t stg = sb + (uint32_t)(c % NSTG) * (2 * TILE_B);
        const int k0 = c * BK;
        #pragma unroll
        for (int i = 0; i < 4; i++) {                   // A tile: 128 rows x 128B
            const int sub = tid + i * 256;
            const int row = sub >> 3, col = sub & 7;
            const fp16* src = bA + (size_t)row * lda + k0 + col * 8;
            uint32_t off = (uint32_t)(row * 128 + col * 16);
            uint32_t dst = stg + (off ^ ((off >> 3) & 0x70));
            asm volatile("cp.async.cg.shared.global [%0], [%1], 16;" :: "r"(dst), "l"(src) : "memory");
        }
        #pragma unroll
        for (int i = 0; i < 4; i++) {                   // V tile: 64 t-rows x 256B
            const int sub = tid + i * 256;
            const int row = sub >> 4, col = sub & 15;
            const fp16* src = bB + (size_t)(k0 + row) * ldb + col * 8;
            uint32_t dst = stg + TILE_B + (uint32_t)(row * 256)
                         + ((uint32_t)(col ^ (row & 7)) << 4);
            asm volatile("cp.async.cg.shared.global [%0], [%1], 16;" :: "r"(dst), "l"(src) : "memory");
        }
        asm volatile("cp.async.commit_group;" ::: "memory");
    };

    const int rlane = (lane & 7) + ((lane >> 3) & 1) * 8;
    const uint32_t xlane = (uint32_t)((rlane & 7) * 16);
    const uint32_t kbl = (uint32_t)((lane >> 4) * 16);
    const uint32_t x7 = (uint32_t)(rlane & 7);
    const uint32_t nch = (uint32_t)((lane >> 4) & 1);
    uint32_t aoff[2], boffT[4], kx[4];
    #pragma unroll
    for (int mf = 0; mf < 2; mf++) aoff[mf] = (uint32_t)((wm * 32 + mf * 16 + rlane) << 7);
    #pragma unroll
    for (int g = 0; g < 4; g++)
        boffT[g] = (uint32_t)(rlane * 256)
                 + ((((uint32_t)(wn * 8 + g * 2) + nch) ^ x7) << 4);
    #pragma unroll
    for (int ks = 0; ks < 4; ks++) kx[ks] = ((uint32_t)(ks * 32) + kbl) ^ xlane;

    float acc[2][8][4] = {};

    load_chunk(0);
    if (NC > 1) load_chunk(1);

    for (int c = 0; c < NC; ++c) {
        if (c + 2 < NC) asm volatile("cp.async.wait_group 1;" ::: "memory");
        else            asm volatile("cp.async.wait_group 0;" ::: "memory");
        __syncthreads();                       // also publishes srinv (first iter)
        if (c + 2 < NC) load_chunk(c + 2);

        const uint32_t stg = sb + (uint32_t)(c % NSTG) * (2 * TILE_B);
        const uint32_t sA_ = stg, sB_ = stg + TILE_B;

        #pragma unroll
        for (int ks = 0; ks < 4; ks++) {
            uint32_t ah[2][4], bf[8][2];
            ldsm4(ah[0], sA_ + aoff[0] + kx[ks]);
            ldsm4(ah[1], sA_ + aoff[1] + kx[ks]);
            #pragma unroll
            for (int g = 0; g < 4; g++) {
                uint32_t t[4];
                ldsm4t(t, sB_ + (uint32_t)(ks * 4096) + boffT[g]);
                bf[2*g][0]   = t[0]; bf[2*g][1]   = t[1];
                bf[2*g+1][0] = t[2]; bf[2*g+1][1] = t[3];
            }
            #pragma unroll
            for (int mf = 0; mf < 2; mf++)
                #pragma unroll
                for (int nf = 0; nf < 8; nf++)
                    mma16816(acc[mf][nf], ah[mf], bf[nf][0], bf[nf][1]);
        }
    }

    const size_t cb = (size_t)blockIdx.z * sC;
    #pragma unroll
    for (int mf = 0; mf < 2; mf++) {
        const int mloc = wm * 32 + mf * 16 + (lane >> 2);
        const int m = m0 + mloc;
        const float i0 = srinv[mloc];
        const float i1 = srinv[mloc + 8];
        #pragma unroll
        for (int nf = 0; nf < 8; nf++) {
            const int n = n0 + wn * 64 + nf * 8 + 2 * (lane & 3);
            float2 o0 = {acc[mf][nf][0] * i0, acc[mf][nf][1] * i0};
            float2 o1 = {acc[mf][nf][2] * i1, acc[mf][nf][3] * i1};
            *reinterpret_cast<float2*>(Cf + cb + (size_t)m * ldc + n)       = o0;
            *reinterpret_cast<float2*>(Cf + cb + (size_t)(m + 8) * ldc + n) = o1;
        }
    }
}

// ---------------- prep: x->fp16 convert | W->W^T fp16 | bias concat (one launch) ----------------
#define CONV_BLKS 8192                       // 8192*1024/4 elems / 256 thr
__global__ __launch_bounds__(256) void prep(
    const float* __restrict__ x, fp16* __restrict__ x16,
    const float* __restrict__ Wq, const float* __restrict__ Wk, const float* __restrict__ Wv,
    const float* __restrict__ bq, const float* __restrict__ bk, const float* __restrict__ bv,
    fp16* __restrict__ wt, float* __restrict__ bias)
{
    const int bid = blockIdx.x;
    const int tid = threadIdx.x;
    if (bid < CONV_BLKS) {                               // x convert (float4 per thread)
        int i = bid * 256 + tid;
        float4 v = reinterpret_cast<const float4*>(x)[i];
        __align__(8) fp16 h[4];
        h[0] = __float2half(v.x); h[1] = __float2half(v.y);
        h[2] = __float2half(v.z); h[3] = __float2half(v.w);
        reinterpret_cast<uint2*>(x16)[i] = *reinterpret_cast<uint2*>(h);
        return;
    }
    // W transpose: 3 * 32x32 tile grid
    __shared__ float t[32][33];
    const int idx = bid - CONV_BLKS;
    const int z = idx >> 10;                             // 1024 tiles per matrix
    const int bx = idx & 31, by = (idx >> 5) & 31;
    const float* W = z == 0 ? Wq : z == 1 ? Wk : Wv;
    fp16* o = wt + (size_t)z * DM * DM;
    const int n0 = bx * 32, k0 = by * 32;
    const int tx = tid & 31, ty = tid >> 5;
    if (bx == 0 && by == 0) {                            // fold bias concat
        const float* b = z == 0 ? bq : z == 1 ? bk : bv;
        #pragma unroll
        for (int j = 0; j < 4; j++)
            bias[z * DM + tid + j * 256] = b[tid + j * 256];
    }
    #pragma unroll
    for (int r = 0; r < 4; r++)
        t[ty + 8 * r][tx] = W[(size_t)(k0 + ty + 8 * r) * DM + n0 + tx];
    __syncthreads();
    #pragma unroll
    for (int r = 0; r < 4; r++)
        o[(size_t)(n0 + ty + 8 * r) * DM + k0 + tx] = __float2half(t[tx][ty + 8 * r]);
}

// ---------------- launcher ----------------
extern "C" void kernel_launch(void* const* d_in, const int* in_sizes, int n_in,
                              void* d_out, int out_size)
{
    const float* x  = (const float*)d_in[0];
    const float* Wq = (const float*)d_in[1];
    const float* bq = (const float*)d_in[2];
    const float* Wk = (const float*)d_in[3];
    const float* bk = (const float*)d_in[4];
    const float* Wv = (const float*)d_in[5];
    const float* bv = (const float*)d_in[6];
    float* out = (float*)d_out;

    fp16 *x16, *wt, *qkv, *sp;
    float *bias, *rspart;
    cudaGetSymbolAddress((void**)&x16, g_x16);
    cudaGetSymbolAddress((void**)&wt, g_wt);
    cudaGetSymbolAddress((void**)&qkv, g_qkv);
    cudaGetSymbolAddress((void**)&sp, g_sp);
    cudaGetSymbolAddress((void**)&bias, g_bias);
    cudaGetSymbolAddress((void**)&rspart, g_rspart);

    cudaFuncSetAttribute(gemmw<0>, cudaFuncAttributeMaxDynamicSharedMemorySize, GSMEM);
    cudaFuncSetAttribute(gemmw<1>, cudaFuncAttributeMaxDynamicSharedMemorySize, GSMEM);
    cudaFuncSetAttribute(gemmv,    cudaFuncAttributeMaxDynamicSharedMemorySize, VSMEM);

    const int M = BATCH * SEQ;

    // 1. prep: convert x, transpose W, concat bias (single launch)
    prep<<<CONV_BLKS + 3 * 1024, 256>>>(x, x16, Wq, Wk, Wv, bq, bk, bv, wt, bias);

    // 2. fused QKV projection: [8192, 3072] = x16 @ wt^T + bias
    gemmw<0><<<dim3(3 * DM / 128, M / 128, 1), 256, GSMEM>>>(
        x16, wt, bias, 1.f, qkv, nullptr,
        DM, DM, DM, 3 * DM, 0, 0, 0);

    // 3. exp(scale * Q @ K^T) -> fp16 (unnormalized) + row-partial sums
    gemmw<1><<<dim3(SEQ / 128, SEQ / 128, BATCH), 256, GSMEM>>>(
        qkv, qkv + DM, nullptr, 0.03125f, sp, rspart,
        DM, 3 * DM, 3 * DM, SEQ,
        (size_t)SEQ * 3 * DM, (size_t)SEQ * 3 * DM, (size_t)SEQ * SEQ);

    // 4. out = (exp @ V) * rinv[row]; rinv reduced in gemmv prologue
    gemmv<<<dim3(DM / 128, SEQ / 128, BATCH), 256, VSMEM>>>(
        sp, qkv + 2 * DM, rspart, out,
        SEQ, SEQ, 3 * DM, DM,
        (size_t)SEQ * SEQ, (size_t)SEQ * 3 * DM, (size_t)SEQ * DM);
}